// round 3
// baseline (speedup 1.0000x reference)
#include <cuda_runtime.h>
#include <cstdint>

#define BATCH    128
#define WTOT     8192
#define DDIM     64
#define SSPLIT   8
#define WSEG     (WTOT / SSPLIT)     // 1024 per CTA
#define WT       64                  // w-chunk per smem tile
#define NCHUNK   (WSEG / WT)         // 16
#define NTHREADS 256

// Scratch: partial Gram matrices and partial column sums (no allocations allowed).
__device__ float g_part[BATCH][SSPLIT][DDIM * DDIM];   // ~16.8 MB
__device__ float s_part[BATCH][SSPLIT][DDIM];

typedef unsigned long long u64;

__device__ __forceinline__ void fma2(u64& acc, u64 a, u64 b) {
    asm("fma.rn.f32x2 %0, %1, %2, %3;" : "=l"(acc) : "l"(a), "l"(b), "l"(acc));
}
__device__ __forceinline__ u64 pack2(float a) {
    u64 r; unsigned ai = __float_as_uint(a);
    asm("mov.b64 %0, {%1, %1};" : "=l"(r) : "r"(ai));
    return r;
}
__device__ __forceinline__ float lo32(u64 v) { return __uint_as_float((unsigned)(v & 0xffffffffull)); }
__device__ __forceinline__ float hi32(u64 v) { return __uint_as_float((unsigned)(v >> 32)); }

__global__ __launch_bounds__(NTHREADS, 2)
void gram_kernel(const float* __restrict__ x) {
    const int s = blockIdx.x;       // W segment
    const int b = blockIdx.y;       // batch
    const int tid = threadIdx.x;
    const int ti = tid >> 4;        // 0..15  -> rows 4*ti..4*ti+3
    const int tj = tid & 15;        // 0..15  -> cols 4*tj..4*tj+3

    __shared__ float tile[2][WT][DDIM];   // 32 KB double-buffered

    const long base = ((long)b * WTOT + (long)s * WSEG) * DDIM;

    u64 acc[8];
#pragma unroll
    for (int k = 0; k < 8; k++) acc[k] = 0ull;
    float s0 = 0.f, s1 = 0.f, s2 = 0.f, s3 = 0.f;
    const bool do_sum = (tj == 0);

    float4 r0, r1, r2, r3;

    // stage chunk 0
    {
        const float4* gp = (const float4*)(x + base);
        r0 = gp[tid]; r1 = gp[tid + 256]; r2 = gp[tid + 512]; r3 = gp[tid + 768];
        float4* sp = (float4*)&tile[0][0][0];
        sp[tid] = r0; sp[tid + 256] = r1; sp[tid + 512] = r2; sp[tid + 768] = r3;
    }
    __syncthreads();

    int buf = 0;
    for (int c = 0; c < NCHUNK; c++) {
        if (c + 1 < NCHUNK) {
            const float4* gp = (const float4*)(x + base + (long)(c + 1) * (WT * DDIM));
            r0 = gp[tid]; r1 = gp[tid + 256]; r2 = gp[tid + 512]; r3 = gp[tid + 768];
        }

        const float* tp = &tile[buf][0][0];
#pragma unroll 4
        for (int w = 0; w < WT; w++) {
            const float* row = tp + (w << 6);
            float4 av = *(const float4*)(row + 4 * ti);
            ulonglong2 bv = *(const ulonglong2*)(row + 4 * tj);  // packed {j0,j1},{j2,j3}
            u64 A0 = pack2(av.x), A1 = pack2(av.y), A2 = pack2(av.z), A3 = pack2(av.w);
            fma2(acc[0], A0, bv.x); fma2(acc[1], A0, bv.y);
            fma2(acc[2], A1, bv.x); fma2(acc[3], A1, bv.y);
            fma2(acc[4], A2, bv.x); fma2(acc[5], A2, bv.y);
            fma2(acc[6], A3, bv.x); fma2(acc[7], A3, bv.y);
            if (do_sum) { s0 += av.x; s1 += av.y; s2 += av.z; s3 += av.w; }
        }
        __syncthreads();
        if (c + 1 < NCHUNK) {
            float4* sp = (float4*)&tile[buf ^ 1][0][0];
            sp[tid] = r0; sp[tid + 256] = r1; sp[tid + 512] = r2; sp[tid + 768] = r3;
        }
        __syncthreads();
        buf ^= 1;
    }

    // write partial Gram [4 rows x 4 cols]
    float* gp = &g_part[b][s][0];
#pragma unroll
    for (int ii = 0; ii < 4; ii++) {
        u64 v0 = acc[2 * ii], v1 = acc[2 * ii + 1];
        int row = (4 * ti + ii) * DDIM + 4 * tj;
        gp[row + 0] = lo32(v0); gp[row + 1] = hi32(v0);
        gp[row + 2] = lo32(v1); gp[row + 3] = hi32(v1);
    }
    if (do_sum) {
        float* sp = &s_part[b][s][0];
        sp[4 * ti + 0] = s0; sp[4 * ti + 1] = s1;
        sp[4 * ti + 2] = s2; sp[4 * ti + 3] = s3;
    }
}

__global__ void finalize_kernel(float* __restrict__ out) {
    const int b = blockIdx.x;
    const int tid = threadIdx.x;

    __shared__ float cov[DDIM * DDIM];
    __shared__ float ssum[DDIM];
    __shared__ float stdv[DDIM];

    // reduce partial Gram
    for (int idx = tid; idx < DDIM * DDIM; idx += NTHREADS) {
        float g = 0.f;
#pragma unroll
        for (int s = 0; s < SSPLIT; s++) g += g_part[b][s][idx];
        cov[idx] = g;
    }
    if (tid < DDIM) {
        float acc = 0.f;
#pragma unroll
        for (int s = 0; s < SSPLIT; s++) acc += s_part[b][s][tid];
        ssum[tid] = acc;
    }
    __syncthreads();

    const float invW  = 1.0f / (float)WTOT;
    const float invW1 = 1.0f / (float)(WTOT - 1);

    if (tid < DDIM) {
        float Si = ssum[tid];
        float c = (cov[tid * DDIM + tid] - Si * Si * invW) * invW1;
        stdv[tid] = sqrtf(c) + 1e-8f;
    }
    __syncthreads();

    if (tid < DDIM) {
        int i = tid;
        float Si = ssum[i];
        float inv_si = 1.0f / stdv[i];
        float cnt = 0.f;
#pragma unroll 8
        for (int j = 0; j < DDIM; j++) {
            float c = (cov[i * DDIM + j] - Si * ssum[j] * invW) * invW1;
            float corr = c * inv_si / stdv[j];
            if (fabsf(corr) > 0.3f) cnt += 1.0f;
        }
        out[b * DDIM + i] = cnt - 1.0f;   // remove self-correlation
    }
}

extern "C" void kernel_launch(void* const* d_in, const int* in_sizes, int n_in,
                              void* d_out, int out_size) {
    const float* x = (const float*)d_in[0];
    float* out = (float*)d_out;

    dim3 grid1(SSPLIT, BATCH);
    gram_kernel<<<grid1, NTHREADS>>>(x);
    finalize_kernel<<<BATCH, NTHREADS>>>(out);
}

// round 6
// speedup vs baseline: 2.8007x; 2.8007x over previous
#include <cuda_runtime.h>
#include <cuda_bf16.h>
#include <cstdint>

#define BATCH    128
#define WTOT     8192
#define DDIM     64
#define SSPLIT   4
#define WSEG     (WTOT / SSPLIT)     // 2048
#define WC       128                 // w per staged tile
#define NTILES   (WSEG / WC)         // 16
#define NTHREADS 256
#define KSTEPS   8                   // 128 w / k16 per mma

// Scratch partials (no allocations allowed)
__device__ float g_part[BATCH][SSPLIT][DDIM * DDIM];   // 8.4 MB
__device__ float s_part[BATCH][SSPLIT][DDIM];

__device__ __forceinline__ uint32_t smem_u32(const void* p) {
    uint32_t a;
    asm("{ .reg .u64 t; cvta.to.shared.u64 t, %1; cvt.u32.u64 %0, t; }" : "=r"(a) : "l"(p));
    return a;
}
__device__ __forceinline__ uint32_t cvt2(float hi, float lo) {
    uint32_t r; asm("cvt.rn.bf16x2.f32 %0, %1, %2;" : "=r"(r) : "f"(hi), "f"(lo)); return r;
}
__device__ __forceinline__ void sts64(uint32_t addr, uint32_t r0, uint32_t r1) {
    asm volatile("st.shared.v2.b32 [%0], {%1, %2};" :: "r"(addr), "r"(r0), "r"(r1) : "memory");
}
__device__ __forceinline__ void ldsm4t(uint32_t& r0, uint32_t& r1, uint32_t& r2, uint32_t& r3,
                                       uint32_t addr) {
    asm volatile("ldmatrix.sync.aligned.m8n8.x4.trans.shared.b16 {%0,%1,%2,%3}, [%4];"
                 : "=r"(r0), "=r"(r1), "=r"(r2), "=r"(r3) : "r"(addr));
}
__device__ __forceinline__ void mma16816(float& d0, float& d1, float& d2, float& d3,
                                         uint32_t a0, uint32_t a1, uint32_t a2, uint32_t a3,
                                         uint32_t b0, uint32_t b1) {
    asm volatile(
        "mma.sync.aligned.m16n8k16.row.col.f32.bf16.bf16.f32 "
        "{%0,%1,%2,%3}, {%4,%5,%6,%7}, {%8,%9}, {%0,%1,%2,%3};"
        : "+f"(d0), "+f"(d1), "+f"(d2), "+f"(d3)
        : "r"(a0), "r"(a1), "r"(a2), "r"(a3), "r"(b0), "r"(b1));
}

// Staging tile: [w][d] bf16, 128 B per row, XOR-swizzled by ((w&7)<<4).
#define SWZ(w, d2bytes) ((uint32_t)((w) * 128 + (d2bytes)) ^ (((uint32_t)(w) & 7u) << 4))

__global__ __launch_bounds__(NTHREADS)
void gram_kernel(const float* __restrict__ x) {
    __shared__ __align__(16) uint8_t stage[2][WC * 128];   // 32 KB double-buffered
    __shared__ float4 sums[256];                            // 4 KB

    const int tid  = threadIdx.x;
    const int wid  = tid >> 5;
    const int lane = tid & 31;
    const int s = blockIdx.x;
    const int b = blockIdx.y;

    const uint32_t stg = smem_u32(&stage[0][0]);

    // Phase A role: float4 index f = tid + 256*i -> w = f/16, d0 = 4*(tid&15)
    const int d0 = 4 * (tid & 15);
    const int w0 = tid >> 4;

    // MMA role: warp -> 16-row stripe i0, 32-col slab jb
    const int i0 = 16 * (wid >> 1);
    const int jb = 32 * (wid & 1);
    // ldmatrix lane-constant offsets (pre-XOR k&7 == lane&7 since k0 % 16 == 0)
    const int kA = (lane & 7) + ((lane & 16) >> 1);
    const int cA = i0 + (lane & 8);
    const uint32_t constA  = (uint32_t)(kA * 128 + cA * 2) ^ (((uint32_t)lane & 7u) << 4);
    const int kB = (lane & 7) + (lane & 8);
    const int cB0 = jb + ((lane & 16) >> 1);        // tiles j, j+8
    const int cB1 = cB0 + 16;                        // tiles j+16, j+24
    const uint32_t constB0 = (uint32_t)(kB * 128 + cB0 * 2) ^ (((uint32_t)lane & 7u) << 4);
    const uint32_t constB1 = (uint32_t)(kB * 128 + cB1 * 2) ^ (((uint32_t)lane & 7u) << 4);

    const float4* gp = (const float4*)(x + ((long)b * WTOT + (long)s * WSEG) * DDIM);

    float4 v[8];
#pragma unroll
    for (int i = 0; i < 8; i++) v[i] = gp[tid + 256 * i];

    float acc[4][4];
#pragma unroll
    for (int t = 0; t < 4; t++)
#pragma unroll
        for (int r = 0; r < 4; r++) acc[t][r] = 0.f;

    float sum0 = 0.f, sum1 = 0.f, sum2 = 0.f, sum3 = 0.f;

#pragma unroll 1
    for (int c = 0; c < NTILES; c++) {
        const uint32_t sbase = stg + (uint32_t)((c & 1) * (WC * 128));

        // ---- Phase A: cvt fp32->bf16, swizzled stage, column sums ----
#pragma unroll
        for (int i = 0; i < 8; i++) {
            uint32_t r0 = cvt2(v[i].y, v[i].x);
            uint32_t r1 = cvt2(v[i].w, v[i].z);
            sum0 += v[i].x; sum1 += v[i].y; sum2 += v[i].z; sum3 += v[i].w;
            const int w = w0 + 16 * i;
            sts64(sbase + SWZ(w, d0 * 2), r0, r1);
        }
        __syncthreads();

        // prefetch next tile (overlaps MMA)
        if (c + 1 < NTILES) {
#pragma unroll
            for (int i = 0; i < 8; i++) v[i] = gp[(c + 1) * 2048 + tid + 256 * i];
        }

        // ---- MMA: G += A^T A over 128 w (8 k-steps of 16) ----
#pragma unroll
        for (int ks = 0; ks < KSTEPS; ks++) {
            const uint32_t kb = sbase + (uint32_t)(ks * 2048);
            uint32_t a0, a1, a2, a3, p0, p1, p2, p3, q0, q1, q2, q3;
            ldsm4t(a0, a1, a2, a3, kb + constA);
            ldsm4t(p0, p1, p2, p3, kb + constB0);
            ldsm4t(q0, q1, q2, q3, kb + constB1);
            mma16816(acc[0][0], acc[0][1], acc[0][2], acc[0][3], a0, a1, a2, a3, p0, p1);
            mma16816(acc[1][0], acc[1][1], acc[1][2], acc[1][3], a0, a1, a2, a3, p2, p3);
            mma16816(acc[2][0], acc[2][1], acc[2][2], acc[2][3], a0, a1, a2, a3, q0, q1);
            mma16816(acc[3][0], acc[3][1], acc[3][2], acc[3][3], a0, a1, a2, a3, q2, q3);
        }
        // No trailing sync needed: next iter writes the other buffer, and the
        // next iter's __syncthreads (after its STS) orders reuse of this one.
    }

    // ---- write Gram partials: warp slab [i0:i0+16) x [jb:jb+32) ----
    {
        const int g = lane >> 2;
        const int col2 = 2 * (lane & 3);
        float* gpart = &g_part[b][s][0];
#pragma unroll
        for (int t = 0; t < 4; t++) {
            const int jcol = jb + 8 * t + col2;
            *(float2*)&gpart[(i0 + g) * DDIM + jcol]     = make_float2(acc[t][0], acc[t][1]);
            *(float2*)&gpart[(i0 + g + 8) * DDIM + jcol] = make_float2(acc[t][2], acc[t][3]);
        }
    }

    // ---- column sums ----
    {
        const int q = tid & 15, p = tid >> 4;
        sums[(q << 4) | p] = make_float4(sum0, sum1, sum2, sum3);
    }
    __syncthreads();
    if (tid < DDIM) {
        const int q = tid >> 2, r = tid & 3;
        const float* sp = (const float*)sums;
        float a = 0.f;
#pragma unroll
        for (int p = 0; p < 16; p++) a += sp[(((q << 4) | p) << 2) + r];
        s_part[b][s][tid] = a;
    }
}

__global__ void finalize_kernel(float* __restrict__ out) {
    const int b = blockIdx.x;
    const int tid = threadIdx.x;

    __shared__ float cov[DDIM * DDIM];
    __shared__ float ssum[DDIM];
    __shared__ float stdv[DDIM];

    // fully-unrolled reduction: 16 independent LDG.128 in flight per thread
    {
        float4 a[4];
#pragma unroll
        for (int k = 0; k < 4; k++) a[k] = make_float4(0.f, 0.f, 0.f, 0.f);
#pragma unroll
        for (int sI = 0; sI < SSPLIT; sI++) {
            const float4* g4 = (const float4*)&g_part[b][sI][0];
#pragma unroll
            for (int k = 0; k < 4; k++) {
                float4 g = g4[tid + 256 * k];
                a[k].x += g.x; a[k].y += g.y; a[k].z += g.z; a[k].w += g.w;
            }
        }
#pragma unroll
        for (int k = 0; k < 4; k++) ((float4*)cov)[tid + 256 * k] = a[k];
    }
    if (tid < DDIM) {
        float a = 0.f;
#pragma unroll
        for (int sI = 0; sI < SSPLIT; sI++) a += s_part[b][sI][tid];
        ssum[tid] = a;
    }
    __syncthreads();

    const float invW  = 1.0f / (float)WTOT;
    const float invW1 = 1.0f / (float)(WTOT - 1);

    if (tid < DDIM) {
        float Si = ssum[tid];
        float c = (cov[tid * DDIM + tid] - Si * Si * invW) * invW1;
        stdv[tid] = sqrtf(c) + 1e-8f;
    }
    __syncthreads();

    if (tid < DDIM) {
        const int i = tid;
        float Si = ssum[i];
        float inv_si = 1.0f / stdv[i];
        float cnt = 0.f;
#pragma unroll 8
        for (int j = 0; j < DDIM; j++) {
            float c = (cov[i * DDIM + j] - Si * ssum[j] * invW) * invW1;
            float corr = c * inv_si / stdv[j];
            if (fabsf(corr) > 0.3f) cnt += 1.0f;
        }
        out[b * DDIM + i] = cnt - 1.0f;
    }
}

extern "C" void kernel_launch(void* const* d_in, const int* in_sizes, int n_in,
                              void* d_out, int out_size) {
    const float* x = (const float*)d_in[0];
    float* out = (float*)d_out;

    dim3 grid1(SSPLIT, BATCH);
    gram_kernel<<<grid1, NTHREADS>>>(x);
    finalize_kernel<<<BATCH, NTHREADS>>>(out);
}

// round 7
// speedup vs baseline: 3.1580x; 1.1276x over previous
#include <cuda_runtime.h>
#include <cuda_bf16.h>
#include <cstdint>

#define BATCH    128
#define WTOT     8192
#define DDIM     64
#define SSPLIT   4
#define WSEG     (WTOT / SSPLIT)     // 2048
#define WC       128                 // w per staged tile
#define NTILES   (WSEG / WC)         // 16
#define NTHREADS 256
#define KSTEPS   8                   // 128 w / k16 per mma

// Scratch partials (no allocations allowed)
__device__ float g_part[BATCH][SSPLIT][DDIM * DDIM];   // upper 16x16 blocks only
__device__ float s_part[BATCH][SSPLIT][DDIM];
__device__ unsigned int done_cnt[BATCH];               // zero-init; reset by finalizer

__device__ __forceinline__ uint32_t smem_u32(const void* p) {
    uint32_t a;
    asm("{ .reg .u64 t; cvta.to.shared.u64 t, %1; cvt.u32.u64 %0, t; }" : "=r"(a) : "l"(p));
    return a;
}
__device__ __forceinline__ uint32_t cvt2(float hi, float lo) {
    uint32_t r; asm("cvt.rn.bf16x2.f32 %0, %1, %2;" : "=r"(r) : "f"(hi), "f"(lo)); return r;
}
__device__ __forceinline__ void sts64(uint32_t addr, uint32_t r0, uint32_t r1) {
    asm volatile("st.shared.v2.b32 [%0], {%1, %2};" :: "r"(addr), "r"(r0), "r"(r1) : "memory");
}
__device__ __forceinline__ void ldsm4t(uint32_t& r0, uint32_t& r1, uint32_t& r2, uint32_t& r3,
                                       uint32_t addr) {
    asm volatile("ldmatrix.sync.aligned.m8n8.x4.trans.shared.b16 {%0,%1,%2,%3}, [%4];"
                 : "=r"(r0), "=r"(r1), "=r"(r2), "=r"(r3) : "r"(addr));
}
__device__ __forceinline__ void mma16816(float* d,
                                         uint32_t a0, uint32_t a1, uint32_t a2, uint32_t a3,
                                         uint32_t b0, uint32_t b1) {
    asm volatile(
        "mma.sync.aligned.m16n8k16.row.col.f32.bf16.bf16.f32 "
        "{%0,%1,%2,%3}, {%4,%5,%6,%7}, {%8,%9}, {%0,%1,%2,%3};"
        : "+f"(d[0]), "+f"(d[1]), "+f"(d[2]), "+f"(d[3])
        : "r"(a0), "r"(a1), "r"(a2), "r"(a3), "r"(b0), "r"(b1));
}

// Staging tile: [w][d] bf16, 128 B per row, XOR-swizzled by ((w&7)<<4).
#define SWZ(w, d2bytes) ((uint32_t)((w) * 128 + (d2bytes)) ^ (((uint32_t)(w) & 7u) << 4))

__global__ __launch_bounds__(NTHREADS)
void gram_kernel(const float* __restrict__ x, float* __restrict__ out) {
    __shared__ __align__(16) uint8_t stage[2][WC * 128];   // 32 KB double-buffered
    __shared__ float4 sums[256];                            // 4 KB
    __shared__ unsigned int lastflag;

    const int tid  = threadIdx.x;
    const int wid  = tid >> 5;
    const int lane = tid & 31;
    const int s = blockIdx.x;
    const int b = blockIdx.y;

    const uint32_t stg = smem_u32(&stage[0][0]);

    // Phase A role
    const int d0 = 4 * (tid & 15);
    const int w0 = tid >> 4;

    // ---- warp -> upper-triangular 16x16 block(s) ----
    int rA, cAb;
    if (wid < 4)      { rA = wid;     cAb = wid;     }
    else if (wid < 7) { rA = 0;       cAb = wid - 3; }
    else              { rA = 1;       cAb = 2;       }
    const bool dual = (wid < 2);
    const int rB = wid + 1, cBb = 3;   // extra blocks (1,3), (2,3)

    const int kA = (lane & 7) + ((lane & 16) >> 1);
    const int kB = (lane & 7) + (lane & 8);
    const uint32_t swx = ((uint32_t)lane & 7u) << 4;
    const int laneA = lane & 8;
    const int laneB = (lane & 16) >> 1;
    const uint32_t oA1 = (uint32_t)(kA * 128 + (16 * rA + laneA) * 2) ^ swx;
    const uint32_t oB1 = (uint32_t)(kB * 128 + (16 * cAb + laneB) * 2) ^ swx;
    const uint32_t oA2 = (uint32_t)(kA * 128 + (16 * rB + laneA) * 2) ^ swx;
    const uint32_t oB2 = (uint32_t)(kB * 128 + (16 * cBb + laneB) * 2) ^ swx;

    const float4* gp = (const float4*)(x + ((long)b * WTOT + (long)s * WSEG) * DDIM);

    float4 v[8];
#pragma unroll
    for (int i = 0; i < 8; i++) v[i] = gp[tid + 256 * i];

    float acc1[2][4], acc2[2][4];
#pragma unroll
    for (int t = 0; t < 2; t++)
#pragma unroll
        for (int r = 0; r < 4; r++) { acc1[t][r] = 0.f; acc2[t][r] = 0.f; }

    float sum0 = 0.f, sum1 = 0.f, sum2 = 0.f, sum3 = 0.f;

#pragma unroll 1
    for (int c = 0; c < NTILES; c++) {
        const uint32_t sbase = stg + (uint32_t)((c & 1) * (WC * 128));

        // ---- Phase A: cvt fp32->bf16, swizzled stage, column sums ----
#pragma unroll
        for (int i = 0; i < 8; i++) {
            uint32_t r0 = cvt2(v[i].y, v[i].x);
            uint32_t r1 = cvt2(v[i].w, v[i].z);
            sum0 += v[i].x; sum1 += v[i].y; sum2 += v[i].z; sum3 += v[i].w;
            const int w = w0 + 16 * i;
            sts64(sbase + SWZ(w, d0 * 2), r0, r1);
        }
        __syncthreads();

        // prefetch next tile (overlaps MMA)
        if (c + 1 < NTILES) {
#pragma unroll
            for (int i = 0; i < 8; i++) v[i] = gp[(c + 1) * 2048 + tid + 256 * i];
        }

        // ---- MMA: upper-tri blocks only ----
#pragma unroll
        for (int ks = 0; ks < KSTEPS; ks++) {
            const uint32_t kb = sbase + (uint32_t)(ks * 2048);
            uint32_t a0, a1, a2, a3, b0, b1, b2, b3;
            ldsm4t(a0, a1, a2, a3, kb + oA1);
            ldsm4t(b0, b1, b2, b3, kb + oB1);
            mma16816(acc1[0], a0, a1, a2, a3, b0, b1);
            mma16816(acc1[1], a0, a1, a2, a3, b2, b3);
            if (dual) {
                ldsm4t(a0, a1, a2, a3, kb + oA2);
                ldsm4t(b0, b1, b2, b3, kb + oB2);
                mma16816(acc2[0], a0, a1, a2, a3, b0, b1);
                mma16816(acc2[1], a0, a1, a2, a3, b2, b3);
            }
        }
    }

    // ---- write Gram partial blocks (upper triangle only) ----
    {
        const int g = lane >> 2;
        const int col2 = 2 * (lane & 3);
        float* gpart = &g_part[b][s][0];
#pragma unroll
        for (int t = 0; t < 2; t++) {
            const int jcol = 16 * cAb + 8 * t + col2;
            *(float2*)&gpart[(16 * rA + g) * DDIM + jcol]     = make_float2(acc1[t][0], acc1[t][1]);
            *(float2*)&gpart[(16 * rA + g + 8) * DDIM + jcol] = make_float2(acc1[t][2], acc1[t][3]);
        }
        if (dual) {
#pragma unroll
            for (int t = 0; t < 2; t++) {
                const int jcol = 16 * cBb + 8 * t + col2;
                *(float2*)&gpart[(16 * rB + g) * DDIM + jcol]     = make_float2(acc2[t][0], acc2[t][1]);
                *(float2*)&gpart[(16 * rB + g + 8) * DDIM + jcol] = make_float2(acc2[t][2], acc2[t][3]);
            }
        }
    }

    // ---- column sums -> s_part ----
    {
        const int q = tid & 15, p = tid >> 4;
        sums[(q << 4) | p] = make_float4(sum0, sum1, sum2, sum3);
    }
    __syncthreads();
    if (tid < DDIM) {
        const int q = tid >> 2, r = tid & 3;
        const float* sp = (const float*)sums;
        float a = 0.f;
#pragma unroll
        for (int p = 0; p < 16; p++) a += sp[(((q << 4) | p) << 2) + r];
        s_part[b][s][tid] = a;
    }

    // ---- arrival protocol: last CTA of this batch finalizes ----
    __threadfence();
    __syncthreads();
    if (tid == 0) {
        unsigned int old = atomicAdd(&done_cnt[b], 1u);
        lastflag = (old == SSPLIT - 1);
        if (lastflag) done_cnt[b] = 0;   // reset for next graph replay
    }
    __syncthreads();
    if (!lastflag) return;
    __threadfence();   // acquire: make peers' partials visible

    // ================= inline finalize (smem reuse) =================
    float* cov  = (float*)&stage[0][0];          // 16 KB
    float* ssum = (float*)&sums[0];              // 64 floats
    float* stdv = ssum + DDIM;                   // 64 floats

    for (int idx = tid; idx < DDIM * DDIM; idx += NTHREADS) {
        const int i = idx >> 6, j = idx & 63;
        const int src = ((i >> 4) <= (j >> 4)) ? idx : (j * DDIM + i);  // mirror lower
        float a = 0.f;
#pragma unroll
        for (int ss = 0; ss < SSPLIT; ss++) a += __ldcg(&g_part[b][ss][src]);
        cov[idx] = a;
    }
    if (tid < DDIM) {
        float a = 0.f;
#pragma unroll
        for (int ss = 0; ss < SSPLIT; ss++) a += __ldcg(&s_part[b][ss][tid]);
        ssum[tid] = a;
    }
    __syncthreads();

    const float invW  = 1.0f / (float)WTOT;
    const float invW1 = 1.0f / (float)(WTOT - 1);

    if (tid < DDIM) {
        float Si = ssum[tid];
        float cc = (cov[tid * DDIM + tid] - Si * Si * invW) * invW1;
        stdv[tid] = sqrtf(cc) + 1e-8f;
    }
    __syncthreads();

    if (tid < DDIM) {
        const int i = tid;
        float Si = ssum[i];
        float inv_si = 1.0f / stdv[i];
        float cnt = 0.f;
#pragma unroll 8
        for (int j = 0; j < DDIM; j++) {
            float cc = (cov[i * DDIM + j] - Si * ssum[j] * invW) * invW1;
            float corr = cc * inv_si / stdv[j];
            if (fabsf(corr) > 0.3f) cnt += 1.0f;
        }
        out[b * DDIM + i] = cnt - 1.0f;
    }
}

extern "C" void kernel_launch(void* const* d_in, const int* in_sizes, int n_in,
                              void* d_out, int out_size) {
    const float* x = (const float*)d_in[0];
    float* out = (float*)d_out;

    dim3 grid(SSPLIT, BATCH);
    gram_kernel<<<grid, NTHREADS>>>(x, out);
}